// round 1
// baseline (speedup 1.0000x reference)
#include <cuda_runtime.h>

// Problem constants
constexpr int PB = 2;      // batch
constexpr int PT = 2048;   // seq len
constexpr int PC = 1024;   // channels
constexpr int PH = 16;     // heads
constexpr int PD = 64;     // head dim
constexpr int PBT = PB * PT;     // 4096
constexpr int PC3 = 3 * PC;      // 3072

// Scratch (device globals — no allocation allowed)
__device__ float g_q[PB * PH * PT * PD];   // [B*H, T, D], pre-scaled by 1/sqrt(D)
__device__ float g_k[PB * PH * PT * PD];
__device__ float g_v[PB * PH * PT * PD];
__device__ float g_att[PBT * PC];          // attention output [B,T,C]

// ---------------------------------------------------------------------------
// SGEMM: Out[m,n] = sum_k A[m,k] * W[n,k] + bias[n]
// 128x128 tile, K-step 8, 256 threads, 8x8 register tile per thread.
// MODE 0: QKV epilogue (scatter to g_q/g_k/g_v head-major, scale Q)
// MODE 1: plain epilogue to Out (row-major, ldc = N)
// ---------------------------------------------------------------------------
template <int MODE>
__global__ __launch_bounds__(256) void sgemm_kernel(
    const float* __restrict__ A,
    const float* __restrict__ W,
    const float* __restrict__ bias,
    float* __restrict__ Out,
    int K, int N)
{
    __shared__ float As[8][128];
    __shared__ float Bs[8][128];

    const int tid = threadIdx.x;
    const int tx = tid & 15;
    const int ty = tid >> 4;
    const int bm = blockIdx.y * 128;
    const int bn = blockIdx.x * 128;

    const float* Ap = (MODE == 1) ? (const float*)g_att : A;

    const int ml = tid >> 1;
    const int kl = (tid & 1) << 2;
    const float* aSrc = Ap + (size_t)(bm + ml) * K + kl;
    const float* bSrc = W  + (size_t)(bn + ml) * K + kl;

    float acc[8][8];
#pragma unroll
    for (int i = 0; i < 8; i++)
#pragma unroll
        for (int j = 0; j < 8; j++) acc[i][j] = 0.0f;

    for (int kt = 0; kt < K; kt += 8) {
        float4 av = *(const float4*)(aSrc + kt);
        float4 bv = *(const float4*)(bSrc + kt);
        __syncthreads();
        As[kl + 0][ml] = av.x; As[kl + 1][ml] = av.y;
        As[kl + 2][ml] = av.z; As[kl + 3][ml] = av.w;
        Bs[kl + 0][ml] = bv.x; Bs[kl + 1][ml] = bv.y;
        Bs[kl + 2][ml] = bv.z; Bs[kl + 3][ml] = bv.w;
        __syncthreads();
#pragma unroll
        for (int kk = 0; kk < 8; kk++) {
            float a[8], b[8];
            *(float4*)(a)     = *(const float4*)&As[kk][ty * 8];
            *(float4*)(a + 4) = *(const float4*)&As[kk][ty * 8 + 4];
            *(float4*)(b)     = *(const float4*)&Bs[kk][tx * 8];
            *(float4*)(b + 4) = *(const float4*)&Bs[kk][tx * 8 + 4];
#pragma unroll
            for (int i = 0; i < 8; i++)
#pragma unroll
                for (int j = 0; j < 8; j++)
                    acc[i][j] = fmaf(a[i], b[j], acc[i][j]);
        }
    }

#pragma unroll
    for (int i = 0; i < 8; i++) {
        const int m = bm + ty * 8 + i;
#pragma unroll
        for (int j = 0; j < 8; j++) {
            const int n = bn + tx * 8 + j;
            float v = acc[i][j] + bias[n];
            if (MODE == 0) {
                const int which = n >> 10;      // 0=q,1=k,2=v
                const int c = n & 1023;
                const int h = c >> 6;
                const int d = c & 63;
                const int b_ = m >> 11;         // T = 2048
                const int t = m & 2047;
                const size_t di = (((size_t)(b_ * PH + h)) * PT + t) * PD + d;
                if (which == 0)      g_q[di] = v * 0.125f;   // 1/sqrt(64)
                else if (which == 1) g_k[di] = v;
                else                 g_v[di] = v;
            } else {
                Out[(size_t)m * N + n] = v;
            }
        }
    }
}

// ---------------------------------------------------------------------------
// Flash attention (causal, fp32). One block per (head, 64-query tile).
// 256 threads: lane map ty=tid/16 (rows, stride 16), tx=tid%16 (cols, stride 16).
// SMEM: Qt (d-major, stride 65), KtP (K d-major stride 65, reused as P row-major
// stride 64), Vs (row-major stride 64). Dynamic smem = 49664 B.
// ---------------------------------------------------------------------------
constexpr int ATTN_SMEM = (2 * 64 * 65 + 64 * 64) * 4;

__global__ __launch_bounds__(256) void attn_kernel()
{
    extern __shared__ float sm[];
    float* Qt  = sm;                  // Qt[d*65 + r]
    float* KtP = sm + 64 * 65;        // Kt[d*65 + r]  /  P[r*64 + c]
    float* Vs  = sm + 2 * 64 * 65;    // Vs[c*64 + d]

    const int tid = threadIdx.x;
    const int tx = tid & 15;
    const int ty = tid >> 4;
    const int qt = blockIdx.x;        // query tile [0, 32)
    const int bh = blockIdx.y;        // b*H + h    [0, 32)

    // Load Q tile (transposed to d-major)
    const float* qp = g_q + ((size_t)bh * PT + qt * 64) * PD;
    for (int f = tid; f < 1024; f += 256) {
        float4 v = ((const float4*)qp)[f];
        const int r = f >> 4;
        const int c = (f & 15) << 2;
        Qt[(c + 0) * 65 + r] = v.x;
        Qt[(c + 1) * 65 + r] = v.y;
        Qt[(c + 2) * 65 + r] = v.z;
        Qt[(c + 3) * 65 + r] = v.w;
    }

    float o[4][4];
    float mrow[4], lrow[4];
#pragma unroll
    for (int i = 0; i < 4; i++) {
        mrow[i] = -3.0e38f;
        lrow[i] = 0.0f;
#pragma unroll
        for (int j = 0; j < 4; j++) o[i][j] = 0.0f;
    }

    for (int kt = 0; kt <= qt; kt++) {
        const float* kp = g_k + ((size_t)bh * PT + kt * 64) * PD;
        const float* vp = g_v + ((size_t)bh * PT + kt * 64) * PD;

        __syncthreads();  // prior iteration's P/V reads (and Q store) complete
        for (int f = tid; f < 1024; f += 256) {
            float4 v = ((const float4*)kp)[f];
            const int r = f >> 4;
            const int c = (f & 15) << 2;
            KtP[(c + 0) * 65 + r] = v.x;
            KtP[(c + 1) * 65 + r] = v.y;
            KtP[(c + 2) * 65 + r] = v.z;
            KtP[(c + 3) * 65 + r] = v.w;
            ((float4*)Vs)[f] = ((const float4*)vp)[f];
        }
        __syncthreads();

        // S = Q K^T (Q pre-scaled)
        float s[4][4];
#pragma unroll
        for (int i = 0; i < 4; i++)
#pragma unroll
            for (int j = 0; j < 4; j++) s[i][j] = 0.0f;

#pragma unroll 16
        for (int d = 0; d < 64; d++) {
            float qv[4], kv[4];
#pragma unroll
            for (int i = 0; i < 4; i++) qv[i] = Qt[d * 65 + ty + 16 * i];
#pragma unroll
            for (int j = 0; j < 4; j++) kv[j] = KtP[d * 65 + tx + 16 * j];
#pragma unroll
            for (int i = 0; i < 4; i++)
#pragma unroll
                for (int j = 0; j < 4; j++)
                    s[i][j] = fmaf(qv[i], kv[j], s[i][j]);
        }

        // Causal mask on the diagonal tile
        if (kt == qt) {
#pragma unroll
            for (int i = 0; i < 4; i++)
#pragma unroll
                for (int j = 0; j < 4; j++)
                    if (tx + 16 * j > ty + 16 * i) s[i][j] = -3.0e38f;
        }

        // Online softmax (row groups = 16 consecutive lanes)
#pragma unroll
        for (int i = 0; i < 4; i++) {
            float mx = fmaxf(fmaxf(s[i][0], s[i][1]), fmaxf(s[i][2], s[i][3]));
#pragma unroll
            for (int off = 1; off < 16; off <<= 1)
                mx = fmaxf(mx, __shfl_xor_sync(0xffffffffu, mx, off));
            const float mnew = fmaxf(mrow[i], mx);
            const float corr = __expf(mrow[i] - mnew);
            mrow[i] = mnew;
            float rs = 0.0f;
#pragma unroll
            for (int j = 0; j < 4; j++) {
                s[i][j] = __expf(s[i][j] - mnew);
                rs += s[i][j];
            }
#pragma unroll
            for (int off = 1; off < 16; off <<= 1)
                rs += __shfl_xor_sync(0xffffffffu, rs, off);
            lrow[i] = lrow[i] * corr + rs;
#pragma unroll
            for (int j = 0; j < 4; j++) o[i][j] *= corr;
        }

        __syncthreads();  // everyone done reading Kt before it becomes P
#pragma unroll
        for (int i = 0; i < 4; i++)
#pragma unroll
            for (int j = 0; j < 4; j++)
                KtP[(ty + 16 * i) * 64 + tx + 16 * j] = s[i][j];
        __syncthreads();

        // O += P V
#pragma unroll 16
        for (int jj = 0; jj < 64; jj++) {
            float pv[4], vv[4];
#pragma unroll
            for (int i = 0; i < 4; i++) pv[i] = KtP[(ty + 16 * i) * 64 + jj];
#pragma unroll
            for (int j = 0; j < 4; j++) vv[j] = Vs[jj * 64 + tx + 16 * j];
#pragma unroll
            for (int i = 0; i < 4; i++)
#pragma unroll
                for (int j = 0; j < 4; j++)
                    o[i][j] = fmaf(pv[i], vv[j], o[i][j]);
        }
    }

    // Normalize and store to [B, T, C]
    const int b_ = bh >> 4;
    const int h = bh & 15;
#pragma unroll
    for (int i = 0; i < 4; i++) {
        const float inv = 1.0f / lrow[i];
        const int t = qt * 64 + ty + 16 * i;
        float* op = g_att + ((size_t)(b_ * PT + t)) * PC + h * 64;
#pragma unroll
        for (int j = 0; j < 4; j++)
            op[tx + 16 * j] = o[i][j] * inv;
    }
}

// ---------------------------------------------------------------------------
extern "C" void kernel_launch(void* const* d_in, const int* in_sizes, int n_in,
                              void* d_out, int out_size)
{
    const float* x      = (const float*)d_in[0];
    const float* attn_w = (const float*)d_in[1];
    const float* attn_b = (const float*)d_in[2];
    const float* proj_w = (const float*)d_in[3];
    const float* proj_b = (const float*)d_in[4];
    float* out = (float*)d_out;

    cudaFuncSetAttribute(attn_kernel,
                         cudaFuncAttributeMaxDynamicSharedMemorySize, ATTN_SMEM);

    // 1) QKV projection + head split + Q pre-scale
    sgemm_kernel<0><<<dim3(PC3 / 128, PBT / 128), 256>>>(
        x, attn_w, attn_b, nullptr, PC, PC3);

    // 2) Causal flash attention
    attn_kernel<<<dim3(PT / 64, PB * PH), 256, ATTN_SMEM>>>();

    // 3) Output projection
    sgemm_kernel<1><<<dim3(PC / 128, PBT / 128), 256>>>(
        nullptr, proj_w, proj_b, out, PC, PC);
}

// round 3
// speedup vs baseline: 2.3226x; 2.3226x over previous
#include <cuda_runtime.h>
#include <cuda_bf16.h>
#include <cstdint>

// Problem constants
constexpr int PB = 2;      // batch
constexpr int PT = 2048;   // seq len
constexpr int PC = 1024;   // channels
constexpr int PH = 16;     // heads
constexpr int PD = 64;     // head dim
constexpr int PBT = PB * PT;     // 4096
constexpr int PC3 = 3 * PC;      // 3072
constexpr int KE = 3 * PC;       // K-expanded: 3072

// ---------------------------------------------------------------------------
// Scratch (device globals — no allocation allowed)
// ---------------------------------------------------------------------------
__device__ float g_q[PB * PH * PT * PD];   // [B*H, T, D], Q pre-scaled by 1/8
__device__ float g_k[PB * PH * PT * PD];
__device__ float g_v[PB * PH * PT * PD];
__device__ float g_att[PBT * PC];          // attention output [B,T,C]

// Split-bf16 K-expanded operands: row-major [rows, 3K]
__device__ __nv_bfloat16 g_xs [PBT * KE];   // x split        (A of QKV gemm)
__device__ __nv_bfloat16 g_ws [PC3 * KE];   // attn_w split   (B of QKV gemm)
__device__ __nv_bfloat16 g_pws[PC  * KE];   // proj_w split   (B of proj gemm)
__device__ __nv_bfloat16 g_as [PBT * KE];   // g_att split    (A of proj gemm)

// ---------------------------------------------------------------------------
// PTX helpers (sm_80-level only: cp.async, ldmatrix, mma.sync)
// ---------------------------------------------------------------------------
__device__ __forceinline__ uint32_t smem_to_u32(const void* p) {
    uint32_t a;
    asm("{ .reg .u64 t; cvta.to.shared.u64 t, %1; cvt.u32.u64 %0, t; }"
        : "=r"(a) : "l"(p));
    return a;
}
__device__ __forceinline__ void cp_async16(uint32_t dst, const void* src) {
    asm volatile("cp.async.cg.shared.global [%0], [%1], 16;" :: "r"(dst), "l"(src));
}
#define CP_ASYNC_COMMIT() asm volatile("cp.async.commit_group;" ::: "memory")
#define CP_ASYNC_WAIT0()  asm volatile("cp.async.wait_group 0;" ::: "memory")

__device__ __forceinline__ void ldsm_x4(uint32_t& r0, uint32_t& r1, uint32_t& r2,
                                        uint32_t& r3, uint32_t addr) {
    asm volatile("ldmatrix.sync.aligned.m8n8.x4.shared.b16 {%0,%1,%2,%3}, [%4];"
        : "=r"(r0), "=r"(r1), "=r"(r2), "=r"(r3) : "r"(addr));
}
__device__ __forceinline__ void mma16816(float* c, const uint32_t* a, const uint32_t* b) {
    asm volatile(
        "mma.sync.aligned.m16n8k16.row.col.f32.bf16.bf16.f32 "
        "{%0,%1,%2,%3}, {%4,%5,%6,%7}, {%8,%9}, {%0,%1,%2,%3};"
        : "+f"(c[0]), "+f"(c[1]), "+f"(c[2]), "+f"(c[3])
        : "r"(a[0]), "r"(a[1]), "r"(a[2]), "r"(a[3]), "r"(b[0]), "r"(b[1]));
}

// ---------------------------------------------------------------------------
// Split kernels: fp32 -> K-expanded split-bf16 [rows, 3K]
// A-side layout: [Ah | Ah | Al];  B-side layout: [Bh | Bl | Bh]
// ---------------------------------------------------------------------------
template <int WHICH>
__global__ __launch_bounds__(256) void split_kernel(const float* __restrict__ src, int total)
{
    int i = blockIdx.x * blockDim.x + threadIdx.x;
    if (i >= total) return;
    const int K = PC;
    int r = i >> 10;
    int k = i & 1023;
    const float* s = (WHICH == 3) ? (const float*)g_att : src;
    float v = s[i];
    __nv_bfloat16 h = __float2bfloat16(v);
    __nv_bfloat16 l = __float2bfloat16(v - __bfloat162float(h));
    __nv_bfloat16* dst =
        (WHICH == 0) ? g_xs : (WHICH == 1) ? g_ws : (WHICH == 2) ? g_pws : g_as;
    size_t base = (size_t)r * KE + k;
    if (WHICH == 0 || WHICH == 3) {
        dst[base] = h; dst[base + K] = h; dst[base + 2 * K] = l;
    } else {
        dst[base] = h; dst[base + K] = l; dst[base + 2 * K] = h;
    }
}

// ---------------------------------------------------------------------------
// HMMA GEMM: Out[m,n] = sum_k A'[m,k] * B'[n,k] + bias[n]
// CTA tile 128x128, 8 warps (4 m x 2 n), warp tile 32x64 of m16n8k16 frags.
// K' = 3072, K-step 32, 96 double-buffered cp.async stages.
// SMEM tiles padded: row stride 40 bf16 = 80 B (conflict-free cp.async + ldmatrix).
// MODE 0: QKV epilogue (scatter into g_q/g_k/g_v head-major, Q scaled 0.125)
// MODE 1: plain epilogue to Out [4096, 1024]
// ---------------------------------------------------------------------------
constexpr int G_STAGES = KE / 32;          // 96
constexpr int LDT      = 40;               // padded row stride (elems)
constexpr int TILE_B   = 128 * LDT * 2;    // 10240 bytes per tile
// smem: [A0][B0][A1][B1]
__shared__ __align__(16) char g_smem_buf[4 * TILE_B];

template <int MODE>
__global__ __launch_bounds__(256) void tc_gemm(
    const float* __restrict__ bias, float* __restrict__ Out)
{
    const uint32_t sb = smem_to_u32(g_smem_buf);
    const int tid  = threadIdx.x;
    const int lane = tid & 31;
    const int wid  = tid >> 5;
    const int warpM = wid & 3;            // 0..3 -> m offset 32*warpM
    const int warpN = wid >> 2;           // 0..1 -> n offset 64*warpN
    const int bm = blockIdx.y * 128;
    const int bn = blockIdx.x * 128;

    const __nv_bfloat16* A = (MODE == 0) ? g_xs : g_as;
    const __nv_bfloat16* B = (MODE == 0) ? g_ws : g_pws;

    // Per-thread load slots: 4 x 16B chunks (2 for A, 2 for B)
    // chunk index space: A: idx in [0,512): row=idx>>2, c=idx&3 ; same for B
    float acc[2][8][4];
#pragma unroll
    for (int i = 0; i < 2; i++)
#pragma unroll
        for (int j = 0; j < 8; j++)
#pragma unroll
            for (int q = 0; q < 4; q++) acc[i][j][q] = 0.0f;

    auto prefetch = [&](int s) {
        const int k0 = s * 32;
        const uint32_t ob = sb + (uint32_t)(s & 1) * (2 * TILE_B);
#pragma unroll
        for (int i = 0; i < 2; i++) {
            int idx = tid + 256 * i;
            int row = idx >> 2, c = idx & 3;
            cp_async16(ob + row * 80 + c * 16,
                       A + (size_t)(bm + row) * KE + k0 + c * 8);
        }
#pragma unroll
        for (int i = 0; i < 2; i++) {
            int idx = tid + 256 * i;
            int row = idx >> 2, c = idx & 3;
            cp_async16(ob + TILE_B + row * 80 + c * 16,
                       B + (size_t)(bn + row) * KE + k0 + c * 8);
        }
        CP_ASYNC_COMMIT();
    };

    prefetch(0);

    // Precomputed per-lane ldmatrix address offsets (within a tile)
    const int a_row = warpM * 32 + (lane & 15);           // + i*16
    const int a_kby = (lane >> 4) * 16;                   // + kk*2
    const int b_row = warpN * 64 + ((lane >> 4) << 3) + (lane & 7);  // + jj*16
    const int b_kby = ((lane >> 3) & 1) * 16;             // + kk*2

    for (int s = 0; s < G_STAGES; s++) {
        CP_ASYNC_WAIT0();
        __syncthreads();
        if (s + 1 < G_STAGES) prefetch(s + 1);

        const uint32_t oA = sb + (uint32_t)(s & 1) * (2 * TILE_B);
        const uint32_t oB = oA + TILE_B;

#pragma unroll
        for (int kk = 0; kk < 32; kk += 16) {
            uint32_t a[2][4];
#pragma unroll
            for (int i = 0; i < 2; i++)
                ldsm_x4(a[i][0], a[i][1], a[i][2], a[i][3],
                        oA + (a_row + i * 16) * 80 + kk * 2 + a_kby);
            uint32_t b[8][2];
#pragma unroll
            for (int jj = 0; jj < 4; jj++) {
                uint32_t r0, r1, r2, r3;
                ldsm_x4(r0, r1, r2, r3,
                        oB + (b_row + jj * 16) * 80 + kk * 2 + b_kby);
                b[2 * jj][0] = r0; b[2 * jj][1] = r1;
                b[2 * jj + 1][0] = r2; b[2 * jj + 1][1] = r3;
            }
#pragma unroll
            for (int i = 0; i < 2; i++)
#pragma unroll
                for (int j = 0; j < 8; j++)
                    mma16816(acc[i][j], a[i], b[j]);
        }
        __syncthreads();
    }

    // Epilogue: thread (lane) holds pairs:
    //   c0,c1 at (r = lane>>2,      n = 2*(lane&3))
    //   c2,c3 at (r = (lane>>2)+8,  n = 2*(lane&3))
#pragma unroll
    for (int i = 0; i < 2; i++) {
#pragma unroll
        for (int j = 0; j < 8; j++) {
            const int n = bn + warpN * 64 + j * 8 + (lane & 3) * 2;
            const float b0 = bias[n], b1 = bias[n + 1];
#pragma unroll
            for (int half = 0; half < 2; half++) {
                const int m = bm + warpM * 32 + i * 16 + (lane >> 2) + half * 8;
                float v0 = acc[i][j][2 * half + 0] + b0;
                float v1 = acc[i][j][2 * half + 1] + b1;
                if (MODE == 0) {
                    const int which = n >> 10;     // 0=q, 1=k, 2=v
                    const int c = n & 1023;
                    const int h = c >> 6;
                    const int d = c & 63;
                    const int b_ = m >> 11;
                    const int t = m & 2047;
                    float* dst = ((which == 0) ? g_q : (which == 1) ? g_k : g_v)
                               + (((size_t)(b_ * PH + h)) * PT + t) * PD + d;
                    if (which == 0) { v0 *= 0.125f; v1 *= 0.125f; }
                    *(float2*)dst = make_float2(v0, v1);
                } else {
                    *(float2*)(Out + (size_t)m * PC + n) = make_float2(v0, v1);
                }
            }
        }
    }
}

// ---------------------------------------------------------------------------
// Flash attention (causal, fp32). One block per (head, 64-query tile).
// ---------------------------------------------------------------------------
constexpr int ATTN_SMEM = (2 * 64 * 65 + 64 * 64) * 4;

__global__ __launch_bounds__(256) void attn_kernel()
{
    extern __shared__ float sm[];
    float* Qt  = sm;                  // Qt[d*65 + r]
    float* KtP = sm + 64 * 65;        // Kt[d*65 + r]  /  P[r*64 + c]
    float* Vs  = sm + 2 * 64 * 65;    // Vs[c*64 + d]

    const int tid = threadIdx.x;
    const int tx = tid & 15;
    const int ty = tid >> 4;
    const int qt = blockIdx.x;
    const int bh = blockIdx.y;

    const float* qp = g_q + ((size_t)bh * PT + qt * 64) * PD;
    for (int f = tid; f < 1024; f += 256) {
        float4 v = ((const float4*)qp)[f];
        const int r = f >> 4;
        const int c = (f & 15) << 2;
        Qt[(c + 0) * 65 + r] = v.x;
        Qt[(c + 1) * 65 + r] = v.y;
        Qt[(c + 2) * 65 + r] = v.z;
        Qt[(c + 3) * 65 + r] = v.w;
    }

    float o[4][4];
    float mrow[4], lrow[4];
#pragma unroll
    for (int i = 0; i < 4; i++) {
        mrow[i] = -3.0e38f;
        lrow[i] = 0.0f;
#pragma unroll
        for (int j = 0; j < 4; j++) o[i][j] = 0.0f;
    }

    for (int kt = 0; kt <= qt; kt++) {
        const float* kp = g_k + ((size_t)bh * PT + kt * 64) * PD;
        const float* vp = g_v + ((size_t)bh * PT + kt * 64) * PD;

        __syncthreads();
        for (int f = tid; f < 1024; f += 256) {
            float4 v = ((const float4*)kp)[f];
            const int r = f >> 4;
            const int c = (f & 15) << 2;
            KtP[(c + 0) * 65 + r] = v.x;
            KtP[(c + 1) * 65 + r] = v.y;
            KtP[(c + 2) * 65 + r] = v.z;
            KtP[(c + 3) * 65 + r] = v.w;
            ((float4*)Vs)[f] = ((const float4*)vp)[f];
        }
        __syncthreads();

        float s[4][4];
#pragma unroll
        for (int i = 0; i < 4; i++)
#pragma unroll
            for (int j = 0; j < 4; j++) s[i][j] = 0.0f;

#pragma unroll 16
        for (int d = 0; d < 64; d++) {
            float qv[4], kv[4];
#pragma unroll
            for (int i = 0; i < 4; i++) qv[i] = Qt[d * 65 + ty + 16 * i];
#pragma unroll
            for (int j = 0; j < 4; j++) kv[j] = KtP[d * 65 + tx + 16 * j];
#pragma unroll
            for (int i = 0; i < 4; i++)
#pragma unroll
                for (int j = 0; j < 4; j++)
                    s[i][j] = fmaf(qv[i], kv[j], s[i][j]);
        }

        if (kt == qt) {
#pragma unroll
            for (int i = 0; i < 4; i++)
#pragma unroll
                for (int j = 0; j < 4; j++)
                    if (tx + 16 * j > ty + 16 * i) s[i][j] = -3.0e38f;
        }

#pragma unroll
        for (int i = 0; i < 4; i++) {
            float mx = fmaxf(fmaxf(s[i][0], s[i][1]), fmaxf(s[i][2], s[i][3]));
#pragma unroll
            for (int off = 1; off < 16; off <<= 1)
                mx = fmaxf(mx, __shfl_xor_sync(0xffffffffu, mx, off));
            const float mnew = fmaxf(mrow[i], mx);
            const float corr = __expf(mrow[i] - mnew);
            mrow[i] = mnew;
            float rs = 0.0f;
#pragma unroll
            for (int j = 0; j < 4; j++) {
                s[i][j] = __expf(s[i][j] - mnew);
                rs += s[i][j];
            }
#pragma unroll
            for (int off = 1; off < 16; off <<= 1)
                rs += __shfl_xor_sync(0xffffffffu, rs, off);
            lrow[i] = lrow[i] * corr + rs;
#pragma unroll
            for (int j = 0; j < 4; j++) o[i][j] *= corr;
        }

        __syncthreads();
#pragma unroll
        for (int i = 0; i < 4; i++)
#pragma unroll
            for (int j = 0; j < 4; j++)
                KtP[(ty + 16 * i) * 64 + tx + 16 * j] = s[i][j];
        __syncthreads();

#pragma unroll 16
        for (int jj = 0; jj < 64; jj++) {
            float pv[4], vv[4];
#pragma unroll
            for (int i = 0; i < 4; i++) pv[i] = KtP[(ty + 16 * i) * 64 + jj];
#pragma unroll
            for (int j = 0; j < 4; j++) vv[j] = Vs[jj * 64 + tx + 16 * j];
#pragma unroll
            for (int i = 0; i < 4; i++)
#pragma unroll
                for (int j = 0; j < 4; j++)
                    o[i][j] = fmaf(pv[i], vv[j], o[i][j]);
        }
    }

    const int b_ = bh >> 4;
    const int h = bh & 15;
#pragma unroll
    for (int i = 0; i < 4; i++) {
        const float inv = 1.0f / lrow[i];
        const int t = qt * 64 + ty + 16 * i;
        float* op = g_att + ((size_t)(b_ * PT + t)) * PC + h * 64;
#pragma unroll
        for (int j = 0; j < 4; j++)
            op[tx + 16 * j] = o[i][j] * inv;
    }
}

// ---------------------------------------------------------------------------
extern "C" void kernel_launch(void* const* d_in, const int* in_sizes, int n_in,
                              void* d_out, int out_size)
{
    const float* x      = (const float*)d_in[0];
    const float* attn_w = (const float*)d_in[1];
    const float* attn_b = (const float*)d_in[2];
    const float* proj_w = (const float*)d_in[3];
    const float* proj_b = (const float*)d_in[4];
    float* out = (float*)d_out;

    cudaFuncSetAttribute(attn_kernel,
                         cudaFuncAttributeMaxDynamicSharedMemorySize, ATTN_SMEM);

    // 0) split fp32 operands into K-expanded split-bf16
    split_kernel<0><<<(PBT * PC + 255) / 256, 256>>>(x, PBT * PC);
    split_kernel<1><<<(PC3 * PC + 255) / 256, 256>>>(attn_w, PC3 * PC);
    split_kernel<2><<<(PC * PC + 255) / 256, 256>>>(proj_w, PC * PC);

    // 1) QKV projection (HMMA) + head split + Q pre-scale
    tc_gemm<0><<<dim3(PC3 / 128, PBT / 128), 256>>>(attn_b, nullptr);

    // 2) Causal flash attention (fp32)
    attn_kernel<<<dim3(PT / 64, PB * PH), 256, ATTN_SMEM>>>();

    // 3) split attention output, then output projection (HMMA)
    split_kernel<3><<<(PBT * PC + 255) / 256, 256>>>(nullptr, PBT * PC);
    tc_gemm<1><<<dim3(PC / 128, PBT / 128), 256>>>(proj_b, out);
}

// round 9
// speedup vs baseline: 4.5888x; 1.9758x over previous
#include <cuda_runtime.h>
#include <cuda_bf16.h>
#include <cstdint>

// Problem constants
constexpr int PB = 2;      // batch
constexpr int PT = 2048;   // seq len
constexpr int PC = 1024;   // channels
constexpr int PH = 16;     // heads
constexpr int PD = 64;     // head dim
constexpr int PBT = PB * PT;     // 4096
constexpr int PC3 = 3 * PC;      // 3072
constexpr int KE = 3 * PC;       // K-expanded: 3072

constexpr float QSCALE = 0.125f * 1.4426950408889634f;  // 1/sqrt(D) * log2(e)

// ---------------------------------------------------------------------------
// Scratch (device globals — no allocation allowed)
// ---------------------------------------------------------------------------
// Head-major [B*H][T][D] bf16 hi/lo pairs (Q pre-scaled into exp2 domain)
__device__ __nv_bfloat16 g_qh[PB * PH * PT * PD];
__device__ __nv_bfloat16 g_ql[PB * PH * PT * PD];
__device__ __nv_bfloat16 g_kh[PB * PH * PT * PD];
__device__ __nv_bfloat16 g_kl[PB * PH * PT * PD];
__device__ __nv_bfloat16 g_vh[PB * PH * PT * PD];
__device__ __nv_bfloat16 g_vl[PB * PH * PT * PD];

// Split-bf16 K-expanded operands: row-major [rows, 3K]
__device__ __nv_bfloat16 g_xs [PBT * KE];   // x split        (A of QKV gemm)
__device__ __nv_bfloat16 g_ws [PC3 * KE];   // attn_w split   (B of QKV gemm)
__device__ __nv_bfloat16 g_pws[PC  * KE];   // proj_w split   (B of proj gemm)
__device__ __nv_bfloat16 g_as [PBT * KE];   // attention out, A-split (proj gemm)

// ---------------------------------------------------------------------------
// PTX helpers (sm_80-level only: cp.async, ldmatrix, mma.sync)
// ---------------------------------------------------------------------------
__device__ __forceinline__ uint32_t smem_to_u32(const void* p) {
    uint32_t a;
    asm("{ .reg .u64 t; cvta.to.shared.u64 t, %1; cvt.u32.u64 %0, t; }"
        : "=r"(a) : "l"(p));
    return a;
}
__device__ __forceinline__ void cp_async16(uint32_t dst, const void* src) {
    asm volatile("cp.async.cg.shared.global [%0], [%1], 16;" :: "r"(dst), "l"(src));
}
#define CP_ASYNC_COMMIT() asm volatile("cp.async.commit_group;" ::: "memory")
#define CP_ASYNC_WAIT0()  asm volatile("cp.async.wait_group 0;" ::: "memory")

__device__ __forceinline__ void ldsm_x4(uint32_t& r0, uint32_t& r1, uint32_t& r2,
                                        uint32_t& r3, uint32_t addr) {
    asm volatile("ldmatrix.sync.aligned.m8n8.x4.shared.b16 {%0,%1,%2,%3}, [%4];"
        : "=r"(r0), "=r"(r1), "=r"(r2), "=r"(r3) : "r"(addr));
}
__device__ __forceinline__ void ldsm_x4_t(uint32_t& r0, uint32_t& r1, uint32_t& r2,
                                          uint32_t& r3, uint32_t addr) {
    asm volatile("ldmatrix.sync.aligned.m8n8.x4.trans.shared.b16 {%0,%1,%2,%3}, [%4];"
        : "=r"(r0), "=r"(r1), "=r"(r2), "=r"(r3) : "r"(addr));
}
__device__ __forceinline__ void mma16816(float* c, const uint32_t* a, const uint32_t* b) {
    asm volatile(
        "mma.sync.aligned.m16n8k16.row.col.f32.bf16.bf16.f32 "
        "{%0,%1,%2,%3}, {%4,%5,%6,%7}, {%8,%9}, {%0,%1,%2,%3};"
        : "+f"(c[0]), "+f"(c[1]), "+f"(c[2]), "+f"(c[3])
        : "r"(a[0]), "r"(a[1]), "r"(a[2]), "r"(a[3]), "r"(b[0]), "r"(b[1]));
}
__device__ __forceinline__ uint32_t packbf2(float lo, float hi) {
    __nv_bfloat162 t = __floats2bfloat162_rn(lo, hi);   // x=lo (low 16 bits)
    return *(uint32_t*)&t;
}

// ---------------------------------------------------------------------------
// Split kernels: fp32 -> K-expanded split-bf16 [rows, 3K]
// A-side layout: [Ah | Ah | Al];  B-side layout: [Bh | Bl | Bh]
// WHICH: 0 = x -> g_xs (A), 1 = attn_w -> g_ws (B), 2 = proj_w -> g_pws (B)
// ---------------------------------------------------------------------------
template <int WHICH>
__global__ __launch_bounds__(256) void split_kernel(const float* __restrict__ src, int total)
{
    int i = blockIdx.x * blockDim.x + threadIdx.x;
    if (i >= total) return;
    const int K = PC;
    int r = i >> 10;
    int k = i & 1023;
    float v = src[i];
    __nv_bfloat16 h = __float2bfloat16(v);
    __nv_bfloat16 l = __float2bfloat16(v - __bfloat162float(h));
    __nv_bfloat16* dst = (WHICH == 0) ? g_xs : (WHICH == 1) ? g_ws : g_pws;
    size_t base = (size_t)r * KE + k;
    if (WHICH == 0) {
        dst[base] = h; dst[base + K] = h; dst[base + 2 * K] = l;
    } else {
        dst[base] = h; dst[base + K] = l; dst[base + 2 * K] = h;
    }
}

// ---------------------------------------------------------------------------
// HMMA GEMM: Out[m,n] = sum_k A'[m,k] * B'[n,k] + bias[n]
// CTA tile 128x128, 8 warps (4 m x 2 n), warp tile 32x64 of m16n8k16 frags.
// MODE 0: QKV epilogue -> bf16 hi/lo scatter into g_{q,k,v}{h,l}, Q in exp2 domain
// MODE 1: plain fp32 epilogue to Out [4096, 1024]
// ---------------------------------------------------------------------------
constexpr int G_STAGES = KE / 32;          // 96
constexpr int TILE_B   = 128 * 40 * 2;     // 10240 bytes per tile (stride 80 B)
__shared__ __align__(16) char g_smem_buf[4 * TILE_B];

template <int MODE>
__global__ __launch_bounds__(256) void tc_gemm(
    const float* __restrict__ bias, float* __restrict__ Out)
{
    const uint32_t sb = smem_to_u32(g_smem_buf);
    const int tid  = threadIdx.x;
    const int lane = tid & 31;
    const int wid  = tid >> 5;
    const int warpM = wid & 3;
    const int warpN = wid >> 2;
    const int bm = blockIdx.y * 128;
    const int bn = blockIdx.x * 128;

    const __nv_bfloat16* A = (MODE == 0) ? g_xs : g_as;
    const __nv_bfloat16* B = (MODE == 0) ? g_ws : g_pws;

    float acc[2][8][4];
#pragma unroll
    for (int i = 0; i < 2; i++)
#pragma unroll
        for (int j = 0; j < 8; j++)
#pragma unroll
            for (int q = 0; q < 4; q++) acc[i][j][q] = 0.0f;

    auto prefetch = [&](int s) {
        const int k0 = s * 32;
        const uint32_t ob = sb + (uint32_t)(s & 1) * (2 * TILE_B);
#pragma unroll
        for (int i = 0; i < 2; i++) {
            int idx = tid + 256 * i;
            int row = idx >> 2, c = idx & 3;
            cp_async16(ob + row * 80 + c * 16,
                       A + (size_t)(bm + row) * KE + k0 + c * 8);
        }
#pragma unroll
        for (int i = 0; i < 2; i++) {
            int idx = tid + 256 * i;
            int row = idx >> 2, c = idx & 3;
            cp_async16(ob + TILE_B + row * 80 + c * 16,
                       B + (size_t)(bn + row) * KE + k0 + c * 8);
        }
        CP_ASYNC_COMMIT();
    };

    prefetch(0);

    const int a_row = warpM * 32 + (lane & 15);
    const int a_kby = (lane >> 4) * 16;
    const int b_row = warpN * 64 + ((lane >> 4) << 3) + (lane & 7);
    const int b_kby = ((lane >> 3) & 1) * 16;

    for (int s = 0; s < G_STAGES; s++) {
        CP_ASYNC_WAIT0();
        __syncthreads();
        if (s + 1 < G_STAGES) prefetch(s + 1);

        const uint32_t oA = sb + (uint32_t)(s & 1) * (2 * TILE_B);
        const uint32_t oB = oA + TILE_B;

#pragma unroll
        for (int kk = 0; kk < 32; kk += 16) {
            uint32_t a[2][4];
#pragma unroll
            for (int i = 0; i < 2; i++)
                ldsm_x4(a[i][0], a[i][1], a[i][2], a[i][3],
                        oA + (a_row + i * 16) * 80 + kk * 2 + a_kby);
            uint32_t b[8][2];
#pragma unroll
            for (int jj = 0; jj < 4; jj++) {
                uint32_t r0, r1, r2, r3;
                ldsm_x4(r0, r1, r2, r3,
                        oB + (b_row + jj * 16) * 80 + kk * 2 + b_kby);
                b[2 * jj][0] = r0; b[2 * jj][1] = r1;
                b[2 * jj + 1][0] = r2; b[2 * jj + 1][1] = r3;
            }
#pragma unroll
            for (int i = 0; i < 2; i++)
#pragma unroll
                for (int j = 0; j < 8; j++)
                    mma16816(acc[i][j], a[i], b[j]);
        }
        __syncthreads();
    }

#pragma unroll
    for (int i = 0; i < 2; i++) {
#pragma unroll
        for (int j = 0; j < 8; j++) {
            const int n = bn + warpN * 64 + j * 8 + (lane & 3) * 2;
            const float b0 = bias[n], b1 = bias[n + 1];
#pragma unroll
            for (int half = 0; half < 2; half++) {
                const int m = bm + warpM * 32 + i * 16 + (lane >> 2) + half * 8;
                float v0 = acc[i][j][2 * half + 0] + b0;
                float v1 = acc[i][j][2 * half + 1] + b1;
                if (MODE == 0) {
                    const int which = n >> 10;     // 0=q, 1=k, 2=v
                    const int c = n & 1023;
                    const int h = c >> 6;
                    const int d = c & 63;
                    const int b_ = m >> 11;
                    const int t = m & 2047;
                    if (which == 0) { v0 *= QSCALE; v1 *= QSCALE; }
                    __nv_bfloat16 h0 = __float2bfloat16(v0);
                    __nv_bfloat16 h1 = __float2bfloat16(v1);
                    __nv_bfloat16 l0 = __float2bfloat16(v0 - __bfloat162float(h0));
                    __nv_bfloat16 l1 = __float2bfloat16(v1 - __bfloat162float(h1));
                    size_t di = (((size_t)(b_ * PH + h)) * PT + t) * PD + d;
                    __nv_bfloat16* dh = (which == 0) ? g_qh : (which == 1) ? g_kh : g_vh;
                    __nv_bfloat16* dl = (which == 0) ? g_ql : (which == 1) ? g_kl : g_vl;
                    *(__nv_bfloat162*)(dh + di) = __halves2bfloat162(h0, h1);
                    *(__nv_bfloat162*)(dl + di) = __halves2bfloat162(l0, l1);
                } else {
                    *(float2*)(Out + (size_t)m * PC + n) = make_float2(v0, v1);
                }
            }
        }
    }
}

// ---------------------------------------------------------------------------
// Flash attention on mma.sync (causal). Block = (head, 128-query tile).
// 8 warps; warp w owns rows qbase + 16w .. +15 (softmax fully warp-local).
// KV tile 64, double-buffered cp.async; hi/lo 3-term products for S and PV.
// SMEM per stage: [Kh][Kl][Vh][Vl], 64 rows x 144 B each (padded, conflict-free).
// Scores already in exp2 domain (Q pre-scaled by log2e/8 in the QKV epilogue).
// ---------------------------------------------------------------------------
constexpr int AT_TILE  = 64 * 144;             // 9216 B
constexpr int AT_STAGE = 4 * AT_TILE;          // 36864 B
constexpr int ATTN_SMEM = 2 * AT_STAGE;        // 73728 B

__global__ __launch_bounds__(256, 1) void attn_mma_kernel()
{
    extern __shared__ char asmem[];
    const uint32_t sb = smem_to_u32(asmem);
    const int tid  = threadIdx.x;
    const int lane = tid & 31;
    const int wid  = tid >> 5;
    const int qt   = 15 - blockIdx.x;          // heavy tiles first
    const int bh   = blockIdx.y;
    const int qbase = qt * 128;
    const int nkv   = 2 * (qt + 1);

    const int lq = lane >> 2;    // row within frag group (0..7)
    const int lr = lane & 3;     // col quad

    // --- Q fragments (hi/lo) resident in registers: rows qbase+wid*16.. ---
    uint32_t qa_h[4][4], qa_l[4][4];
    {
        const size_t qoff = ((size_t)bh * PT + qbase + wid * 16) * PD;
        const __nv_bfloat16* qh = g_qh + qoff;
        const __nv_bfloat16* ql = g_ql + qoff;
#pragma unroll
        for (int ks = 0; ks < 4; ks++) {
            const int c = ks * 16 + lr * 2;
            qa_h[ks][0] = *(const uint32_t*)(qh + lq * 64 + c);
            qa_h[ks][1] = *(const uint32_t*)(qh + (lq + 8) * 64 + c);
            qa_h[ks][2] = *(const uint32_t*)(qh + lq * 64 + c + 8);
            qa_h[ks][3] = *(const uint32_t*)(qh + (lq + 8) * 64 + c + 8);
            qa_l[ks][0] = *(const uint32_t*)(ql + lq * 64 + c);
            qa_l[ks][1] = *(const uint32_t*)(ql + (lq + 8) * 64 + c);
            qa_l[ks][2] = *(const uint32_t*)(ql + lq * 64 + c + 8);
            qa_l[ks][3] = *(const uint32_t*)(ql + (lq + 8) * 64 + c + 8);
        }
    }

    auto prefetchKV = [&](int t) {
        const size_t base = ((size_t)bh * PT + t * 64) * PD;
        const uint32_t ob = sb + (uint32_t)(t & 1) * AT_STAGE;
#pragma unroll
        for (int i = 0; i < 8; i++) {
            int idx = tid + 256 * i;            // 0..2047
            int arr = idx >> 9;                 // 0:Kh 1:Kl 2:Vh 3:Vl
            int row = (idx >> 3) & 63;
            int c   = idx & 7;
            const __nv_bfloat16* src =
                (arr == 0) ? g_kh : (arr == 1) ? g_kl : (arr == 2) ? g_vh : g_vl;
            cp_async16(ob + arr * AT_TILE + row * 144 + c * 16,
                       src + base + row * 64 + c * 8);
        }
        CP_ASYNC_COMMIT();
    };

    prefetchKV(0);

    // ldmatrix lane-address bases (within a 64x144B tile)
    const uint32_t kb = ((((lane >> 4) << 3) + (lane & 7)) * 144) + ((lane >> 3) & 1) * 16;
    const uint32_t vb = (((lane & 7) + ((lane >> 3) & 1) * 8) * 144) + (lane >> 4) * 16;

    float acc_o[8][4];
#pragma unroll
    for (int j = 0; j < 8; j++)
#pragma unroll
        for (int q = 0; q < 4; q++) acc_o[j][q] = 0.0f;
    float m0 = -1e30f, m1 = -1e30f, l0 = 0.0f, l1 = 0.0f;

    for (int t = 0; t < nkv; t++) {
        CP_ASYNC_WAIT0();
        __syncthreads();
        if (t + 1 < nkv) prefetchKV(t + 1);

        const uint32_t ob  = sb + (uint32_t)(t & 1) * AT_STAGE;
        const uint32_t oKh = ob;
        const uint32_t oKl = ob + AT_TILE;
        const uint32_t oVh = ob + 2 * AT_TILE;
        const uint32_t oVl = ob + 3 * AT_TILE;
        const int s0 = t * 64;

        // ---- S = Qh*Kh + Qh*Kl + Ql*Kh ----
        float sacc[8][4];
#pragma unroll
        for (int j = 0; j < 8; j++)
#pragma unroll
            for (int q = 0; q < 4; q++) sacc[j][q] = 0.0f;

#pragma unroll
        for (int ks = 0; ks < 4; ks++) {
            uint32_t bh_[8][2], bl_[8][2];
#pragma unroll
            for (int jj = 0; jj < 4; jj++) {
                uint32_t r0, r1, r2, r3;
                ldsm_x4(r0, r1, r2, r3, oKh + kb + jj * (16 * 144) + ks * 32);
                bh_[2 * jj][0] = r0; bh_[2 * jj][1] = r1;
                bh_[2 * jj + 1][0] = r2; bh_[2 * jj + 1][1] = r3;
                ldsm_x4(r0, r1, r2, r3, oKl + kb + jj * (16 * 144) + ks * 32);
                bl_[2 * jj][0] = r0; bl_[2 * jj][1] = r1;
                bl_[2 * jj + 1][0] = r2; bl_[2 * jj + 1][1] = r3;
            }
#pragma unroll
            for (int j = 0; j < 8; j++) {
                mma16816(sacc[j], qa_h[ks], bh_[j]);
                mma16816(sacc[j], qa_h[ks], bl_[j]);
                mma16816(sacc[j], qa_l[ks], bh_[j]);
            }
        }

        // ---- causal mask: needed iff tile max s exceeds warp's FIRST row ----
        if (s0 + 63 > qbase + wid * 16) {
            const int r0g = qbase + wid * 16 + lq;
#pragma unroll
            for (int j = 0; j < 8; j++) {
                const int cg = s0 + j * 8 + lr * 2;
                if (cg     > r0g)     sacc[j][0] = -1e30f;
                if (cg + 1 > r0g)     sacc[j][1] = -1e30f;
                if (cg     > r0g + 8) sacc[j][2] = -1e30f;
                if (cg + 1 > r0g + 8) sacc[j][3] = -1e30f;
            }
        }

        // ---- online softmax (exp2 domain), rows lq and lq+8 ----
        float tm0 = -1e30f, tm1 = -1e30f;
#pragma unroll
        for (int j = 0; j < 8; j++) {
            tm0 = fmaxf(tm0, fmaxf(sacc[j][0], sacc[j][1]));
            tm1 = fmaxf(tm1, fmaxf(sacc[j][2], sacc[j][3]));
        }
        tm0 = fmaxf(tm0, __shfl_xor_sync(0xffffffffu, tm0, 1));
        tm0 = fmaxf(tm0, __shfl_xor_sync(0xffffffffu, tm0, 2));
        tm1 = fmaxf(tm1, __shfl_xor_sync(0xffffffffu, tm1, 1));
        tm1 = fmaxf(tm1, __shfl_xor_sync(0xffffffffu, tm1, 2));

        const float mn0 = fmaxf(m0, tm0);
        const float mn1 = fmaxf(m1, tm1);
        const float c0 = exp2f(m0 - mn0);
        const float c1 = exp2f(m1 - mn1);
        m0 = mn0; m1 = mn1;

        float rs0 = 0.0f, rs1 = 0.0f;
#pragma unroll
        for (int j = 0; j < 8; j++) {
            sacc[j][0] = exp2f(sacc[j][0] - mn0);
            sacc[j][1] = exp2f(sacc[j][1] - mn0);
            sacc[j][2] = exp2f(sacc[j][2] - mn1);
            sacc[j][3] = exp2f(sacc[j][3] - mn1);
            rs0 += sacc[j][0] + sacc[j][1];
            rs1 += sacc[j][2] + sacc[j][3];
        }
        rs0 += __shfl_xor_sync(0xffffffffu, rs0, 1);
        rs0 += __shfl_xor_sync(0xffffffffu, rs0, 2);
        rs1 += __shfl_xor_sync(0xffffffffu, rs1, 1);
        rs1 += __shfl_xor_sync(0xffffffffu, rs1, 2);
        l0 = l0 * c0 + rs0;
        l1 = l1 * c1 + rs1;

#pragma unroll
        for (int j = 0; j < 8; j++) {
            acc_o[j][0] *= c0; acc_o[j][1] *= c0;
            acc_o[j][2] *= c1; acc_o[j][3] *= c1;
        }

        // ---- O += Ph*Vh + Ph*Vl + Pl*Vh  (P from registers) ----
#pragma unroll
        for (int ks = 0; ks < 4; ks++) {
            uint32_t pa_h[4], pa_l[4];
#pragma unroll
            for (int half = 0; half < 2; half++) {
                const float p0 = sacc[2 * ks + half][0];
                const float p1 = sacc[2 * ks + half][1];
                const float p2 = sacc[2 * ks + half][2];
                const float p3 = sacc[2 * ks + half][3];
                __nv_bfloat16 h0 = __float2bfloat16(p0);
                __nv_bfloat16 h1 = __float2bfloat16(p1);
                __nv_bfloat16 h2 = __float2bfloat16(p2);
                __nv_bfloat16 h3 = __float2bfloat16(p3);
                __nv_bfloat162 hv01 = __halves2bfloat162(h0, h1);
                __nv_bfloat162 hv23 = __halves2bfloat162(h2, h3);
                pa_h[0 + 2 * half] = *(uint32_t*)&hv01;   // (r, k) even/odd
                pa_h[1 + 2 * half] = *(uint32_t*)&hv23;   // (r+8, k)
                pa_l[0 + 2 * half] = packbf2(p0 - __bfloat162float(h0),
                                             p1 - __bfloat162float(h1));
                pa_l[1 + 2 * half] = packbf2(p2 - __bfloat162float(h2),
                                             p3 - __bfloat162float(h3));
            }

            uint32_t bvh[8][2], bvl[8][2];
#pragma unroll
            for (int f = 0; f < 4; f++) {
                uint32_t r0, r1, r2, r3;
                ldsm_x4_t(r0, r1, r2, r3, oVh + vb + ks * (16 * 144) + f * 32);
                bvh[2 * f][0] = r0; bvh[2 * f][1] = r1;
                bvh[2 * f + 1][0] = r2; bvh[2 * f + 1][1] = r3;
                ldsm_x4_t(r0, r1, r2, r3, oVl + vb + ks * (16 * 144) + f * 32);
                bvl[2 * f][0] = r0; bvl[2 * f][1] = r1;
                bvl[2 * f + 1][0] = r2; bvl[2 * f + 1][1] = r3;
            }
#pragma unroll
            for (int j = 0; j < 8; j++) {
                mma16816(acc_o[j], pa_h, bvh[j]);
                mma16816(acc_o[j], pa_h, bvl[j]);
                mma16816(acc_o[j], pa_l, bvh[j]);
            }
        }
    }

    // ---- epilogue: normalize, split hi/lo, write K-expanded g_as rows ----
    const float inv0 = 1.0f / l0;
    const float inv1 = 1.0f / l1;
    const int b_ = bh >> 4;
    const int h  = bh & 15;
    const int t0 = qbase + wid * 16 + lq;
    const int t1 = t0 + 8;
    const size_t row0 = (size_t)(b_ * PT + t0) * KE + h * 64;
    const size_t row1 = (size_t)(b_ * PT + t1) * KE + h * 64;

#pragma unroll
    for (int j = 0; j < 8; j++) {
        const int d = j * 8 + lr * 2;
        {
            float v0 = acc_o[j][0] * inv0, v1 = acc_o[j][1] * inv0;
            __nv_bfloat16 h0 = __float2bfloat16(v0);
            __nv_bfloat16 h1 = __float2bfloat16(v1);
            __nv_bfloat162 hv = __halves2bfloat162(h0, h1);
            uint32_t hp = *(uint32_t*)&hv;
            uint32_t lp = packbf2(v0 - __bfloat162float(h0), v1 - __bfloat162float(h1));
            *(uint32_t*)(g_as + row0 + d)            = hp;
            *(uint32_t*)(g_as + row0 + PC + d)       = hp;
            *(uint32_t*)(g_as + row0 + 2 * PC + d)   = lp;
        }
        {
            float v0 = acc_o[j][2] * inv1, v1 = acc_o[j][3] * inv1;
            __nv_bfloat16 h0 = __float2bfloat16(v0);
            __nv_bfloat16 h1 = __float2bfloat16(v1);
            __nv_bfloat162 hv = __halves2bfloat162(h0, h1);
            uint32_t hp = *(uint32_t*)&hv;
            uint32_t lp = packbf2(v0 - __bfloat162float(h0), v1 - __bfloat162float(h1));
            *(uint32_t*)(g_as + row1 + d)            = hp;
            *(uint32_t*)(g_as + row1 + PC + d)       = hp;
            *(uint32_t*)(g_as + row1 + 2 * PC + d)   = lp;
        }
    }
}

// ---------------------------------------------------------------------------
extern "C" void kernel_launch(void* const* d_in, const int* in_sizes, int n_in,
                              void* d_out, int out_size)
{
    const float* x      = (const float*)d_in[0];
    const float* attn_w = (const float*)d_in[1];
    const float* attn_b = (const float*)d_in[2];
    const float* proj_w = (const float*)d_in[3];
    const float* proj_b = (const float*)d_in[4];
    float* out = (float*)d_out;

    cudaFuncSetAttribute(attn_mma_kernel,
                         cudaFuncAttributeMaxDynamicSharedMemorySize, ATTN_SMEM);

    // 0) split fp32 operands into K-expanded split-bf16
    split_kernel<0><<<(PBT * PC + 255) / 256, 256>>>(x, PBT * PC);
    split_kernel<1><<<(PC3 * PC + 255) / 256, 256>>>(attn_w, PC3 * PC);
    split_kernel<2><<<(PC * PC + 255) / 256, 256>>>(proj_w, PC * PC);

    // 1) QKV projection (HMMA) + head split + hi/lo write + Q exp2-domain scale
    tc_gemm<0><<<dim3(PC3 / 128, PBT / 128), 256>>>(attn_b, nullptr);

    // 2) Causal flash attention (mma.sync, 3-term hi/lo)
    attn_mma_kernel<<<dim3(PT / 128, PB * PH), 256, ATTN_SMEM>>>();

    // 3) Output projection (HMMA) — reads g_as written by attention epilogue
    tc_gemm<1><<<dim3(PC / 128, PBT / 128), 256>>>(proj_b, out);
}

// round 10
// speedup vs baseline: 5.0407x; 1.0985x over previous
#include <cuda_runtime.h>
#include <cuda_bf16.h>
#include <cstdint>

// Problem constants
constexpr int PB = 2;      // batch
constexpr int PT = 2048;   // seq len
constexpr int PC = 1024;   // channels
constexpr int PH = 16;     // heads
constexpr int PD = 64;     // head dim
constexpr int PBT = PB * PT;     // 4096
constexpr int PC3 = 3 * PC;      // 3072

constexpr float QSCALE = 0.125f * 1.4426950408889634f;  // 1/sqrt(D) * log2(e)

// ---------------------------------------------------------------------------
// Scratch (device globals — no allocation allowed)
// ---------------------------------------------------------------------------
// Head-major [B*H][T][D] bf16 hi/lo pairs (Q pre-scaled into exp2 domain)
__device__ __nv_bfloat16 g_qh[PB * PH * PT * PD];
__device__ __nv_bfloat16 g_ql[PB * PH * PT * PD];
__device__ __nv_bfloat16 g_kh[PB * PH * PT * PD];
__device__ __nv_bfloat16 g_kl[PB * PH * PT * PD];
__device__ __nv_bfloat16 g_vh[PB * PH * PT * PD];
__device__ __nv_bfloat16 g_vl[PB * PH * PT * PD];

// Separate hi/lo split operands, plain [rows, K] row-major
__device__ __nv_bfloat16 g_xh [PBT * PC];   // x hi            (A of QKV gemm)
__device__ __nv_bfloat16 g_xl [PBT * PC];   // x lo
__device__ __nv_bfloat16 g_wh [PC3 * PC];   // attn_w hi       (B of QKV gemm)
__device__ __nv_bfloat16 g_wl [PC3 * PC];   // attn_w lo
__device__ __nv_bfloat16 g_pwh[PC  * PC];   // proj_w hi       (B of proj gemm)
__device__ __nv_bfloat16 g_pwl[PC  * PC];   // proj_w lo
__device__ __nv_bfloat16 g_ash[PBT * PC];   // attention out hi (A of proj gemm)
__device__ __nv_bfloat16 g_asl[PBT * PC];   // attention out lo

// ---------------------------------------------------------------------------
// PTX helpers (sm_80-level only: cp.async, ldmatrix, mma.sync)
// ---------------------------------------------------------------------------
__device__ __forceinline__ uint32_t smem_to_u32(const void* p) {
    uint32_t a;
    asm("{ .reg .u64 t; cvta.to.shared.u64 t, %1; cvt.u32.u64 %0, t; }"
        : "=r"(a) : "l"(p));
    return a;
}
__device__ __forceinline__ void cp_async16(uint32_t dst, const void* src) {
    asm volatile("cp.async.cg.shared.global [%0], [%1], 16;" :: "r"(dst), "l"(src));
}
#define CP_ASYNC_COMMIT() asm volatile("cp.async.commit_group;" ::: "memory")
#define CP_ASYNC_WAIT0()  asm volatile("cp.async.wait_group 0;" ::: "memory")

__device__ __forceinline__ void ldsm_x4(uint32_t& r0, uint32_t& r1, uint32_t& r2,
                                        uint32_t& r3, uint32_t addr) {
    asm volatile("ldmatrix.sync.aligned.m8n8.x4.shared.b16 {%0,%1,%2,%3}, [%4];"
        : "=r"(r0), "=r"(r1), "=r"(r2), "=r"(r3) : "r"(addr));
}
__device__ __forceinline__ void ldsm_x4_t(uint32_t& r0, uint32_t& r1, uint32_t& r2,
                                          uint32_t& r3, uint32_t addr) {
    asm volatile("ldmatrix.sync.aligned.m8n8.x4.trans.shared.b16 {%0,%1,%2,%3}, [%4];"
        : "=r"(r0), "=r"(r1), "=r"(r2), "=r"(r3) : "r"(addr));
}
__device__ __forceinline__ void mma16816(float* c, const uint32_t* a, const uint32_t* b) {
    asm volatile(
        "mma.sync.aligned.m16n8k16.row.col.f32.bf16.bf16.f32 "
        "{%0,%1,%2,%3}, {%4,%5,%6,%7}, {%8,%9}, {%0,%1,%2,%3};"
        : "+f"(c[0]), "+f"(c[1]), "+f"(c[2]), "+f"(c[3])
        : "r"(a[0]), "r"(a[1]), "r"(a[2]), "r"(a[3]), "r"(b[0]), "r"(b[1]));
}
__device__ __forceinline__ uint32_t packbf2(float lo, float hi) {
    __nv_bfloat162 t = __floats2bfloat162_rn(lo, hi);   // x=lo (low 16 bits)
    return *(uint32_t*)&t;
}

// ---------------------------------------------------------------------------
// Split kernels: fp32 -> separate hi/lo bf16 arrays (same shape as src)
// WHICH: 0 = x -> g_xh/g_xl, 1 = attn_w -> g_wh/g_wl, 2 = proj_w -> g_pwh/g_pwl
// ---------------------------------------------------------------------------
template <int WHICH>
__global__ __launch_bounds__(256) void split_kernel(const float* __restrict__ src, int total)
{
    int i = blockIdx.x * blockDim.x + threadIdx.x;
    if (i >= total) return;
    float v = src[i];
    __nv_bfloat16 h = __float2bfloat16(v);
    __nv_bfloat16 l = __float2bfloat16(v - __bfloat162float(h));
    __nv_bfloat16* dh = (WHICH == 0) ? g_xh : (WHICH == 1) ? g_wh : g_pwh;
    __nv_bfloat16* dl = (WHICH == 0) ? g_xl : (WHICH == 1) ? g_wl : g_pwl;
    dh[i] = h;
    dl[i] = l;
}

// ---------------------------------------------------------------------------
// HMMA GEMM (3-term hi/lo): Out = Ah*Bh^T + Ah*Bl^T + Al*Bh^T + bias
// CTA tile 128x128, 8 warps (4 m x 2 n), warp tile 32x64 of m16n8k16 frags.
// K = 1024 in 32 stages of 32; per stage loads 4 tiles (Ah, Al, Bh, Bl),
// double-buffered cp.async. SMEM rows padded to 80 B (conflict-free).
// MODE 0: QKV epilogue -> bf16 hi/lo scatter into g_{q,k,v}{h,l}, Q exp2 scale
// MODE 1: plain fp32 epilogue to Out [4096, 1024]
// ---------------------------------------------------------------------------
constexpr int G_STAGES = PC / 32;          // 32
constexpr int TILE_B   = 128 * 80;         // 10240 B per tile (stride 80 B)
constexpr int STAGE_B  = 4 * TILE_B;       // 40960 B per stage
__shared__ __align__(16) char g_smem_buf[2 * STAGE_B];   // 81920 B

template <int MODE>
__global__ __launch_bounds__(256, 2) void tc_gemm(
    const float* __restrict__ bias, float* __restrict__ Out)
{
    const uint32_t sb = smem_to_u32(g_smem_buf);
    const int tid  = threadIdx.x;
    const int lane = tid & 31;
    const int wid  = tid >> 5;
    const int warpM = wid & 3;
    const int warpN = wid >> 2;
    const int bm = blockIdx.y * 128;
    const int bn = blockIdx.x * 128;

    const __nv_bfloat16* Ah = (MODE == 0) ? g_xh : g_ash;
    const __nv_bfloat16* Al = (MODE == 0) ? g_xl : g_asl;
    const __nv_bfloat16* Bh = (MODE == 0) ? g_wh : g_pwh;
    const __nv_bfloat16* Bl = (MODE == 0) ? g_wl : g_pwl;

    float acc[2][8][4];
#pragma unroll
    for (int i = 0; i < 2; i++)
#pragma unroll
        for (int j = 0; j < 8; j++)
#pragma unroll
            for (int q = 0; q < 4; q++) acc[i][j][q] = 0.0f;

    auto prefetch = [&](int s) {
        const int k0 = s * 32;
        const uint32_t ob = sb + (uint32_t)(s & 1) * STAGE_B;
#pragma unroll
        for (int i = 0; i < 8; i++) {
            int idx = tid + 256 * i;            // [0, 2048)
            int tile = idx >> 9;                // 0:Ah 1:Al 2:Bh 3:Bl
            int j   = idx & 511;
            int row = j >> 2;
            int c   = j & 3;
            const __nv_bfloat16* sp =
                (tile == 0) ? Ah : (tile == 1) ? Al : (tile == 2) ? Bh : Bl;
            const int rbase = (tile < 2) ? bm : bn;
            cp_async16(ob + (uint32_t)tile * TILE_B + row * 80 + c * 16,
                       sp + (size_t)(rbase + row) * PC + k0 + c * 8);
        }
        CP_ASYNC_COMMIT();
    };

    prefetch(0);

    const int a_row = warpM * 32 + (lane & 15);
    const int a_kby = (lane >> 4) * 16;
    const int b_row = warpN * 64 + ((lane >> 4) << 3) + (lane & 7);
    const int b_kby = ((lane >> 3) & 1) * 16;

    for (int s = 0; s < G_STAGES; s++) {
        CP_ASYNC_WAIT0();
        __syncthreads();
        if (s + 1 < G_STAGES) prefetch(s + 1);

        const uint32_t ob  = sb + (uint32_t)(s & 1) * STAGE_B;
        const uint32_t oAh = ob;
        const uint32_t oAl = ob + TILE_B;
        const uint32_t oBh = ob + 2 * TILE_B;
        const uint32_t oBl = ob + 3 * TILE_B;

#pragma unroll
        for (int kk = 0; kk < 32; kk += 16) {
            uint32_t a_h[2][4], a_l[2][4];
#pragma unroll
            for (int i = 0; i < 2; i++) {
                ldsm_x4(a_h[i][0], a_h[i][1], a_h[i][2], a_h[i][3],
                        oAh + (a_row + i * 16) * 80 + kk * 2 + a_kby);
                ldsm_x4(a_l[i][0], a_l[i][1], a_l[i][2], a_l[i][3],
                        oAl + (a_row + i * 16) * 80 + kk * 2 + a_kby);
            }
            uint32_t b[8][2];
            // --- Bh: accumulate Ah*Bh and Al*Bh ---
#pragma unroll
            for (int jj = 0; jj < 4; jj++) {
                uint32_t r0, r1, r2, r3;
                ldsm_x4(r0, r1, r2, r3,
                        oBh + (b_row + jj * 16) * 80 + kk * 2 + b_kby);
                b[2 * jj][0] = r0; b[2 * jj][1] = r1;
                b[2 * jj + 1][0] = r2; b[2 * jj + 1][1] = r3;
            }
#pragma unroll
            for (int i = 0; i < 2; i++)
#pragma unroll
                for (int j = 0; j < 8; j++) {
                    mma16816(acc[i][j], a_h[i], b[j]);
                    mma16816(acc[i][j], a_l[i], b[j]);
                }
            // --- Bl: accumulate Ah*Bl (reuse b registers) ---
#pragma unroll
            for (int jj = 0; jj < 4; jj++) {
                uint32_t r0, r1, r2, r3;
                ldsm_x4(r0, r1, r2, r3,
                        oBl + (b_row + jj * 16) * 80 + kk * 2 + b_kby);
                b[2 * jj][0] = r0; b[2 * jj][1] = r1;
                b[2 * jj + 1][0] = r2; b[2 * jj + 1][1] = r3;
            }
#pragma unroll
            for (int i = 0; i < 2; i++)
#pragma unroll
                for (int j = 0; j < 8; j++)
                    mma16816(acc[i][j], a_h[i], b[j]);
        }
        __syncthreads();
    }

#pragma unroll
    for (int i = 0; i < 2; i++) {
#pragma unroll
        for (int j = 0; j < 8; j++) {
            const int n = bn + warpN * 64 + j * 8 + (lane & 3) * 2;
            const float b0 = bias[n], b1 = bias[n + 1];
#pragma unroll
            for (int half = 0; half < 2; half++) {
                const int m = bm + warpM * 32 + i * 16 + (lane >> 2) + half * 8;
                float v0 = acc[i][j][2 * half + 0] + b0;
                float v1 = acc[i][j][2 * half + 1] + b1;
                if (MODE == 0) {
                    const int which = n >> 10;     // 0=q, 1=k, 2=v
                    const int c = n & 1023;
                    const int h = c >> 6;
                    const int d = c & 63;
                    const int b_ = m >> 11;
                    const int t = m & 2047;
                    if (which == 0) { v0 *= QSCALE; v1 *= QSCALE; }
                    __nv_bfloat16 h0 = __float2bfloat16(v0);
                    __nv_bfloat16 h1 = __float2bfloat16(v1);
                    __nv_bfloat16 l0 = __float2bfloat16(v0 - __bfloat162float(h0));
                    __nv_bfloat16 l1 = __float2bfloat16(v1 - __bfloat162float(h1));
                    size_t di = (((size_t)(b_ * PH + h)) * PT + t) * PD + d;
                    __nv_bfloat16* dh = (which == 0) ? g_qh : (which == 1) ? g_kh : g_vh;
                    __nv_bfloat16* dl = (which == 0) ? g_ql : (which == 1) ? g_kl : g_vl;
                    *(__nv_bfloat162*)(dh + di) = __halves2bfloat162(h0, h1);
                    *(__nv_bfloat162*)(dl + di) = __halves2bfloat162(l0, l1);
                } else {
                    *(float2*)(Out + (size_t)m * PC + n) = make_float2(v0, v1);
                }
            }
        }
    }
}

// ---------------------------------------------------------------------------
// Flash attention on mma.sync (causal). Block = (head, 128-query tile).
// 8 warps; warp w owns rows qbase + 16w .. +15 (softmax fully warp-local).
// KV tile 64, double-buffered cp.async; hi/lo 3-term products for S and PV.
// SMEM per stage: [Kh][Kl][Vh][Vl], 64 rows x 144 B each (padded, conflict-free).
// Scores already in exp2 domain (Q pre-scaled by log2e/8 in the QKV epilogue).
// ---------------------------------------------------------------------------
constexpr int AT_TILE  = 64 * 144;             // 9216 B
constexpr int AT_STAGE = 4 * AT_TILE;          // 36864 B
constexpr int ATTN_SMEM = 2 * AT_STAGE;        // 73728 B

__global__ __launch_bounds__(256, 1) void attn_mma_kernel()
{
    extern __shared__ char asmem[];
    const uint32_t sb = smem_to_u32(asmem);
    const int tid  = threadIdx.x;
    const int lane = tid & 31;
    const int wid  = tid >> 5;
    const int qt   = 15 - blockIdx.x;          // heavy tiles first
    const int bh   = blockIdx.y;
    const int qbase = qt * 128;
    const int nkv   = 2 * (qt + 1);

    const int lq = lane >> 2;    // row within frag group (0..7)
    const int lr = lane & 3;     // col quad

    // --- Q fragments (hi/lo) resident in registers: rows qbase+wid*16.. ---
    uint32_t qa_h[4][4], qa_l[4][4];
    {
        const size_t qoff = ((size_t)bh * PT + qbase + wid * 16) * PD;
        const __nv_bfloat16* qh = g_qh + qoff;
        const __nv_bfloat16* ql = g_ql + qoff;
#pragma unroll
        for (int ks = 0; ks < 4; ks++) {
            const int c = ks * 16 + lr * 2;
            qa_h[ks][0] = *(const uint32_t*)(qh + lq * 64 + c);
            qa_h[ks][1] = *(const uint32_t*)(qh + (lq + 8) * 64 + c);
            qa_h[ks][2] = *(const uint32_t*)(qh + lq * 64 + c + 8);
            qa_h[ks][3] = *(const uint32_t*)(qh + (lq + 8) * 64 + c + 8);
            qa_l[ks][0] = *(const uint32_t*)(ql + lq * 64 + c);
            qa_l[ks][1] = *(const uint32_t*)(ql + (lq + 8) * 64 + c);
            qa_l[ks][2] = *(const uint32_t*)(ql + lq * 64 + c + 8);
            qa_l[ks][3] = *(const uint32_t*)(ql + (lq + 8) * 64 + c + 8);
        }
    }

    auto prefetchKV = [&](int t) {
        const size_t base = ((size_t)bh * PT + t * 64) * PD;
        const uint32_t ob = sb + (uint32_t)(t & 1) * AT_STAGE;
#pragma unroll
        for (int i = 0; i < 8; i++) {
            int idx = tid + 256 * i;            // 0..2047
            int arr = idx >> 9;                 // 0:Kh 1:Kl 2:Vh 3:Vl
            int row = (idx >> 3) & 63;
            int c   = idx & 7;
            const __nv_bfloat16* src =
                (arr == 0) ? g_kh : (arr == 1) ? g_kl : (arr == 2) ? g_vh : g_vl;
            cp_async16(ob + arr * AT_TILE + row * 144 + c * 16,
                       src + base + row * 64 + c * 8);
        }
        CP_ASYNC_COMMIT();
    };

    prefetchKV(0);

    // ldmatrix lane-address bases (within a 64x144B tile)
    const uint32_t kb = ((((lane >> 4) << 3) + (lane & 7)) * 144) + ((lane >> 3) & 1) * 16;
    const uint32_t vb = (((lane & 7) + ((lane >> 3) & 1) * 8) * 144) + (lane >> 4) * 16;

    float acc_o[8][4];
#pragma unroll
    for (int j = 0; j < 8; j++)
#pragma unroll
        for (int q = 0; q < 4; q++) acc_o[j][q] = 0.0f;
    float m0 = -1e30f, m1 = -1e30f, l0 = 0.0f, l1 = 0.0f;

    for (int t = 0; t < nkv; t++) {
        CP_ASYNC_WAIT0();
        __syncthreads();
        if (t + 1 < nkv) prefetchKV(t + 1);

        const uint32_t ob  = sb + (uint32_t)(t & 1) * AT_STAGE;
        const uint32_t oKh = ob;
        const uint32_t oKl = ob + AT_TILE;
        const uint32_t oVh = ob + 2 * AT_TILE;
        const uint32_t oVl = ob + 3 * AT_TILE;
        const int s0 = t * 64;

        // ---- S = Qh*Kh + Qh*Kl + Ql*Kh ----
        float sacc[8][4];
#pragma unroll
        for (int j = 0; j < 8; j++)
#pragma unroll
            for (int q = 0; q < 4; q++) sacc[j][q] = 0.0f;

#pragma unroll
        for (int ks = 0; ks < 4; ks++) {
            uint32_t bh_[8][2], bl_[8][2];
#pragma unroll
            for (int jj = 0; jj < 4; jj++) {
                uint32_t r0, r1, r2, r3;
                ldsm_x4(r0, r1, r2, r3, oKh + kb + jj * (16 * 144) + ks * 32);
                bh_[2 * jj][0] = r0; bh_[2 * jj][1] = r1;
                bh_[2 * jj + 1][0] = r2; bh_[2 * jj + 1][1] = r3;
                ldsm_x4(r0, r1, r2, r3, oKl + kb + jj * (16 * 144) + ks * 32);
                bl_[2 * jj][0] = r0; bl_[2 * jj][1] = r1;
                bl_[2 * jj + 1][0] = r2; bl_[2 * jj + 1][1] = r3;
            }
#pragma unroll
            for (int j = 0; j < 8; j++) {
                mma16816(sacc[j], qa_h[ks], bh_[j]);
                mma16816(sacc[j], qa_h[ks], bl_[j]);
                mma16816(sacc[j], qa_l[ks], bh_[j]);
            }
        }

        // ---- causal mask: needed iff tile max s exceeds warp's FIRST row ----
        if (s0 + 63 > qbase + wid * 16) {
            const int r0g = qbase + wid * 16 + lq;
#pragma unroll
            for (int j = 0; j < 8; j++) {
                const int cg = s0 + j * 8 + lr * 2;
                if (cg     > r0g)     sacc[j][0] = -1e30f;
                if (cg + 1 > r0g)     sacc[j][1] = -1e30f;
                if (cg     > r0g + 8) sacc[j][2] = -1e30f;
                if (cg + 1 > r0g + 8) sacc[j][3] = -1e30f;
            }
        }

        // ---- online softmax (exp2 domain), rows lq and lq+8 ----
        float tm0 = -1e30f, tm1 = -1e30f;
#pragma unroll
        for (int j = 0; j < 8; j++) {
            tm0 = fmaxf(tm0, fmaxf(sacc[j][0], sacc[j][1]));
            tm1 = fmaxf(tm1, fmaxf(sacc[j][2], sacc[j][3]));
        }
        tm0 = fmaxf(tm0, __shfl_xor_sync(0xffffffffu, tm0, 1));
        tm0 = fmaxf(tm0, __shfl_xor_sync(0xffffffffu, tm0, 2));
        tm1 = fmaxf(tm1, __shfl_xor_sync(0xffffffffu, tm1, 1));
        tm1 = fmaxf(tm1, __shfl_xor_sync(0xffffffffu, tm1, 2));

        const float mn0 = fmaxf(m0, tm0);
        const float mn1 = fmaxf(m1, tm1);
        const float c0 = exp2f(m0 - mn0);
        const float c1 = exp2f(m1 - mn1);
        m0 = mn0; m1 = mn1;

        float rs0 = 0.0f, rs1 = 0.0f;
#pragma unroll
        for (int j = 0; j < 8; j++) {
            sacc[j][0] = exp2f(sacc[j][0] - mn0);
            sacc[j][1] = exp2f(sacc[j][1] - mn0);
            sacc[j][2] = exp2f(sacc[j][2] - mn1);
            sacc[j][3] = exp2f(sacc[j][3] - mn1);
            rs0 += sacc[j][0] + sacc[j][1];
            rs1 += sacc[j][2] + sacc[j][3];
        }
        rs0 += __shfl_xor_sync(0xffffffffu, rs0, 1);
        rs0 += __shfl_xor_sync(0xffffffffu, rs0, 2);
        rs1 += __shfl_xor_sync(0xffffffffu, rs1, 1);
        rs1 += __shfl_xor_sync(0xffffffffu, rs1, 2);
        l0 = l0 * c0 + rs0;
        l1 = l1 * c1 + rs1;

#pragma unroll
        for (int j = 0; j < 8; j++) {
            acc_o[j][0] *= c0; acc_o[j][1] *= c0;
            acc_o[j][2] *= c1; acc_o[j][3] *= c1;
        }

        // ---- O += Ph*Vh + Ph*Vl + Pl*Vh  (P from registers) ----
#pragma unroll
        for (int ks = 0; ks < 4; ks++) {
            uint32_t pa_h[4], pa_l[4];
#pragma unroll
            for (int half = 0; half < 2; half++) {
                const float p0 = sacc[2 * ks + half][0];
                const float p1 = sacc[2 * ks + half][1];
                const float p2 = sacc[2 * ks + half][2];
                const float p3 = sacc[2 * ks + half][3];
                __nv_bfloat16 h0 = __float2bfloat16(p0);
                __nv_bfloat16 h1 = __float2bfloat16(p1);
                __nv_bfloat16 h2 = __float2bfloat16(p2);
                __nv_bfloat16 h3 = __float2bfloat16(p3);
                __nv_bfloat162 hv01 = __halves2bfloat162(h0, h1);
                __nv_bfloat162 hv23 = __halves2bfloat162(h2, h3);
                pa_h[0 + 2 * half] = *(uint32_t*)&hv01;   // (r, k) even/odd
                pa_h[1 + 2 * half] = *(uint32_t*)&hv23;   // (r+8, k)
                pa_l[0 + 2 * half] = packbf2(p0 - __bfloat162float(h0),
                                             p1 - __bfloat162float(h1));
                pa_l[1 + 2 * half] = packbf2(p2 - __bfloat162float(h2),
                                             p3 - __bfloat162float(h3));
            }

            uint32_t bvh[8][2], bvl[8][2];
#pragma unroll
            for (int f = 0; f < 4; f++) {
                uint32_t r0, r1, r2, r3;
                ldsm_x4_t(r0, r1, r2, r3, oVh + vb + ks * (16 * 144) + f * 32);
                bvh[2 * f][0] = r0; bvh[2 * f][1] = r1;
                bvh[2 * f + 1][0] = r2; bvh[2 * f + 1][1] = r3;
                ldsm_x4_t(r0, r1, r2, r3, oVl + vb + ks * (16 * 144) + f * 32);
                bvl[2 * f][0] = r0; bvl[2 * f][1] = r1;
                bvl[2 * f + 1][0] = r2; bvl[2 * f + 1][1] = r3;
            }
#pragma unroll
            for (int j = 0; j < 8; j++) {
                mma16816(acc_o[j], pa_h, bvh[j]);
                mma16816(acc_o[j], pa_h, bvl[j]);
                mma16816(acc_o[j], pa_l, bvh[j]);
            }
        }
    }

    // ---- epilogue: normalize, split hi/lo, write g_ash/g_asl rows ----
    const float inv0 = 1.0f / l0;
    const float inv1 = 1.0f / l1;
    const int b_ = bh >> 4;
    const int h  = bh & 15;
    const int t0 = qbase + wid * 16 + lq;
    const int t1 = t0 + 8;
    const size_t row0 = (size_t)(b_ * PT + t0) * PC + h * 64;
    const size_t row1 = (size_t)(b_ * PT + t1) * PC + h * 64;

#pragma unroll
    for (int j = 0; j < 8; j++) {
        const int d = j * 8 + lr * 2;
        {
            float v0 = acc_o[j][0] * inv0, v1 = acc_o[j][1] * inv0;
            __nv_bfloat16 h0 = __float2bfloat16(v0);
            __nv_bfloat16 h1 = __float2bfloat16(v1);
            __nv_bfloat162 hv = __halves2bfloat162(h0, h1);
            *(uint32_t*)(g_ash + row0 + d) = *(uint32_t*)&hv;
            *(uint32_t*)(g_asl + row0 + d) =
                packbf2(v0 - __bfloat162float(h0), v1 - __bfloat162float(h1));
        }
        {
            float v0 = acc_o[j][2] * inv1, v1 = acc_o[j][3] * inv1;
            __nv_bfloat16 h0 = __float2bfloat16(v0);
            __nv_bfloat16 h1 = __float2bfloat16(v1);
            __nv_bfloat162 hv = __halves2bfloat162(h0, h1);
            *(uint32_t*)(g_ash + row1 + d) = *(uint32_t*)&hv;
            *(uint32_t*)(g_asl + row1 + d) =
                packbf2(v0 - __bfloat162float(h0), v1 - __bfloat162float(h1));
        }
    }
}

// ---------------------------------------------------------------------------
extern "C" void kernel_launch(void* const* d_in, const int* in_sizes, int n_in,
                              void* d_out, int out_size)
{
    const float* x      = (const float*)d_in[0];
    const float* attn_w = (const float*)d_in[1];
    const float* attn_b = (const float*)d_in[2];
    const float* proj_w = (const float*)d_in[3];
    const float* proj_b = (const float*)d_in[4];
    float* out = (float*)d_out;

    cudaFuncSetAttribute(attn_mma_kernel,
                         cudaFuncAttributeMaxDynamicSharedMemorySize, ATTN_SMEM);

    // 0) split fp32 operands into separate hi/lo bf16 arrays
    split_kernel<0><<<(PBT * PC + 255) / 256, 256>>>(x, PBT * PC);
    split_kernel<1><<<(PC3 * PC + 255) / 256, 256>>>(attn_w, PC3 * PC);
    split_kernel<2><<<(PC * PC + 255) / 256, 256>>>(proj_w, PC * PC);

    // 1) QKV projection (HMMA, 3-term hi/lo) + head split + Q exp2-domain scale
    tc_gemm<0><<<dim3(PC3 / 128, PBT / 128), 256>>>(attn_b, nullptr);

    // 2) Causal flash attention (mma.sync, 3-term hi/lo)
    attn_mma_kernel<<<dim3(PT / 128, PB * PH), 256, ATTN_SMEM>>>();

    // 3) Output projection (HMMA) — reads g_ash/g_asl from attention epilogue
    tc_gemm<1><<<dim3(PC / 128, PBT / 128), 256>>>(proj_b, out);
}